// round 8
// baseline (speedup 1.0000x reference)
#include <cuda_runtime.h>
#include <math.h>
#include <stdint.h>

#define B_    2
#define S_    2048
#define HID_  2048
#define NH_   16
#define QLR_  1536
#define KVLR_ 512
#define DN_   128
#define DR_   64
#define DV_   128
#define DQK_  192
#define MTOT  (B_ * S_)            // 4096
#define CKVW  (KVLR_ + DR_)        // 576
#define QW    (NH_ * DQK_)         // 3072
#define KVW   (NH_ * (DN_ + DV_))  // 4096
#define AOW   (NH_ * DV_)          // 2048
#define SCALE_CONST 0.07216878364870322f   // 192^-0.5

// ---------------- scratch (no allocation allowed) ----------------
__device__ float g_qa [(size_t)MTOT * QLR_];
__device__ float g_ckv[(size_t)MTOT * CKVW];
__device__ float g_q  [(size_t)MTOT * QW];
__device__ float g_kv [(size_t)MTOT * KVW];
__device__ float g_ao [(size_t)MTOT * AOW];
__device__ float g_vt [(size_t)B_ * NH_ * DV_ * S_];   // V transposed: [b][h][vd][s]

// ---------------- helpers ----------------
__device__ __forceinline__ uint32_t f2tf(float f) {
    uint32_t u;
    asm("cvt.rna.tf32.f32 %0, %1;" : "=r"(u) : "f"(f));
    return u;
}

__device__ __forceinline__ void ldsm4(uint32_t* r, uint32_t addr) {
    asm volatile("ldmatrix.sync.aligned.m8n8.x4.shared.b16 {%0,%1,%2,%3},[%4];"
                 : "=r"(r[0]), "=r"(r[1]), "=r"(r[2]), "=r"(r[3]) : "r"(addr));
}

__device__ __forceinline__ void mma_tf32(float4& d, const uint32_t* a, uint32_t b0, uint32_t b1) {
    asm volatile("mma.sync.aligned.m16n8k8.row.col.f32.tf32.tf32.f32 "
                 "{%0,%1,%2,%3},{%4,%5,%6,%7},{%8,%9},{%0,%1,%2,%3};"
                 : "+f"(d.x), "+f"(d.y), "+f"(d.z), "+f"(d.w)
                 : "r"(a[0]), "r"(a[1]), "r"(a[2]), "r"(a[3]), "r"(b0), "r"(b1));
}

__device__ __forceinline__ void cpa16(uint32_t dst, const void* src) {
    asm volatile("cp.async.cg.shared.global [%0], [%1], 16;" :: "r"(dst), "l"(src));
}
#define CP_COMMIT() asm volatile("cp.async.commit_group;")
#define CP_WAIT0()  asm volatile("cp.async.wait_group 0;")
#define CP_WAIT1()  asm volatile("cp.async.wait_group 1;")

// ---------------- tf32 GEMM: C[M,N] = A[M,K] @ Bm[K,N] (unchanged) ----------------
#define GBM 128
#define GBN 128
#define GBK 32
#define ALD 36
#define BLD 132
#define GEMM_A_FLOATS (GBM * ALD)   // 4608
#define GEMM_B_FLOATS (GBK * BLD)   // 4224
#define GEMM_SMEM_BYTES (3 * (GEMM_A_FLOATS + GEMM_B_FLOATS) * 4)   // 105984

__global__ __launch_bounds__(256, 2) void gemm_tf32(
    const float* __restrict__ A, int lda,
    const float* __restrict__ Bm, int ldb,
    float* __restrict__ C, int ldc,
    int M, int N, int K,
    float* __restrict__ vtp)
{
    extern __shared__ float gsm[];
    float* As = gsm;
    float* Bs = gsm + 3 * GEMM_A_FLOATS;

    int tid = threadIdx.x;
    int m0 = blockIdx.y * GBM, n0 = blockIdx.x * GBN;
    int warp = tid >> 5, lane = tid & 31;
    int wm = (warp & 1) * 64, wn = (warp >> 1) * 32;
    int r = lane >> 2, qd = lane & 3;

    float4 acc[4][4];
#pragma unroll
    for (int i = 0; i < 4; i++)
#pragma unroll
        for (int j = 0; j < 4; j++) acc[i][j] = make_float4(0.f, 0.f, 0.f, 0.f);

    int a_row = ((lane >> 3) & 1) * 8 + (lane & 7);
    int a_col = ((lane >> 4) & 1) * 4;
    uint32_t as_u = (uint32_t)__cvta_generic_to_shared(As);
    uint32_t bs_u = (uint32_t)__cvta_generic_to_shared(Bs);

    int s_arow = tid >> 3, s_akc = (tid & 7) * 4;
    int s_krow = tid >> 5, bnc = (lane & 31) * 4;
    bool nok = (n0 + bnc) < N;

    int nk = K / GBK;

#define GEMM_ISSUE(stage, k0)                                                      \
    do {                                                                           \
        uint32_t ad = as_u + (uint32_t)(stage) * GEMM_A_FLOATS * 4;                \
        uint32_t bd = bs_u + (uint32_t)(stage) * GEMM_B_FLOATS * 4;                \
        _Pragma("unroll")                                                          \
        for (int it = 0; it < 4; it++) {                                           \
            int row = s_arow + it * 32;                                            \
            cpa16(ad + (row * ALD + s_akc) * 4,                                    \
                  &A[(size_t)(m0 + row) * lda + (k0) + s_akc]);                    \
        }                                                                          \
        if (nok) {                                                                 \
            _Pragma("unroll")                                                      \
            for (int it = 0; it < 4; it++) {                                       \
                int kk2 = s_krow + it * 8;                                         \
                cpa16(bd + (kk2 * BLD + bnc) * 4,                                  \
                      &Bm[(size_t)((k0) + kk2) * ldb + n0 + bnc]);                 \
            }                                                                      \
        }                                                                          \
    } while (0)

    GEMM_ISSUE(0, 0);
    CP_COMMIT();
    if (nk > 1) GEMM_ISSUE(1, GBK);
    CP_COMMIT();

    for (int t = 0; t < nk; t++) {
        CP_WAIT1();
        __syncthreads();
        if (t + 2 < nk) GEMM_ISSUE((t + 2) % 3, (t + 2) * GBK);
        CP_COMMIT();

        int s = t % 3;
        uint32_t a_base = as_u + (uint32_t)s * GEMM_A_FLOATS * 4;
        const float* bsp = Bs + s * GEMM_B_FLOATS;

#pragma unroll
        for (int ks = 0; ks < 4; ks++) {
            int kk = ks * 8;
            uint32_t af[4][4];
#pragma unroll
            for (int mt = 0; mt < 4; mt++) {
                ldsm4(af[mt], a_base + ((wm + mt * 16 + a_row) * ALD + kk + a_col) * 4);
#pragma unroll
                for (int i = 0; i < 4; i++)
                    af[mt][i] = f2tf(__uint_as_float(af[mt][i]));
            }
            uint32_t b0[4], b1[4];
#pragma unroll
            for (int nt = 0; nt < 4; nt++) {
                const float* p = &bsp[(kk + qd) * BLD + wn + nt * 8 + r];
                b0[nt] = f2tf(p[0]);
                b1[nt] = f2tf(p[4 * BLD]);
            }
#pragma unroll
            for (int mt = 0; mt < 4; mt++)
#pragma unroll
                for (int nt = 0; nt < 4; nt++)
                    mma_tf32(acc[mt][nt], af[mt], b0[nt], b1[nt]);
        }
    }
#undef GEMM_ISSUE

    int row_l = lane >> 2, col_l = (lane & 3) * 2;
#pragma unroll
    for (int mt = 0; mt < 4; mt++) {
#pragma unroll
        for (int nt = 0; nt < 4; nt++) {
            int rr = m0 + wm + mt * 16 + row_l;
            int cc = n0 + wn + nt * 8 + col_l;
            if (cc >= N) continue;
            float4 a = acc[mt][nt];
            if (vtp != nullptr && (cc & 255) >= 128) {
                int hh = cc >> 8, vd = (cc & 255) - 128;
                int bb = rr >> 11, ss = rr & 2047;
                size_t base = ((size_t)(bb * NH_ + hh) * DV_ + vd) * (size_t)S_;
                vtp[base + ss]          = a.x;
                vtp[base + S_ + ss]     = a.y;
                vtp[base + ss + 8]      = a.z;
                vtp[base + S_ + ss + 8] = a.w;
            } else {
                *(float2*)&C[(size_t)rr * ldc + cc]       = make_float2(a.x, a.y);
                *(float2*)&C[(size_t)(rr + 8) * ldc + cc] = make_float2(a.z, a.w);
            }
        }
    }
}

// ---------------- rmsnorm (in place) ----------------
__global__ __launch_bounds__(256) void rmsnorm_kernel(float* __restrict__ x, int stride, int D,
                                                      const float* __restrict__ w)
{
    int row = blockIdx.x;
    float* p = x + (size_t)row * stride;
    float ss = 0.f;
    for (int i = threadIdx.x; i < D; i += 256) { float v = p[i]; ss += v * v; }
    __shared__ float red[8];
#pragma unroll
    for (int off = 16; off; off >>= 1) ss += __shfl_down_sync(0xffffffffu, ss, off);
    if ((threadIdx.x & 31) == 0) red[threadIdx.x >> 5] = ss;
    __syncthreads();
    if (threadIdx.x == 0) {
        float t = 0.f;
#pragma unroll
        for (int i = 0; i < 8; i++) t += red[i];
        red[0] = rsqrtf(t / (float)D + 1e-6f);
    }
    __syncthreads();
    float inv = red[0];
    for (int i = threadIdx.x; i < D; i += 256) p[i] = p[i] * inv * w[i];
}

// ---------------- RoPE ----------------
__global__ void rope_q_kernel(float* __restrict__ q, const float* __restrict__ cosb,
                              const float* __restrict__ sinb)
{
    int idx = blockIdx.x * blockDim.x + threadIdx.x;
    if (idx >= MTOT * NH_ * 32) return;
    int j = idx & 31;
    int h = (idx >> 5) & (NH_ - 1);
    int m = idx >> 9;
    int s = m & (S_ - 1);
    float* base = q + (size_t)m * QW + h * DQK_ + DN_;
    float x = base[j], y = base[j + 32];
    float c0 = cosb[s * DR_ + j],      s0 = sinb[s * DR_ + j];
    float c1 = cosb[s * DR_ + j + 32], s1 = sinb[s * DR_ + j + 32];
    base[j]      = x * c0 - y * s0;
    base[j + 32] = y * c1 + x * s1;
}

__global__ void rope_k_kernel(float* __restrict__ ckv, const float* __restrict__ cosb,
                              const float* __restrict__ sinb)
{
    int idx = blockIdx.x * blockDim.x + threadIdx.x;
    if (idx >= MTOT * 32) return;
    int j = idx & 31;
    int m = idx >> 5;
    int s = m & (S_ - 1);
    float* base = ckv + (size_t)m * CKVW + KVLR_;
    float x = base[j], y = base[j + 32];
    float c0 = cosb[s * DR_ + j],      s0 = sinb[s * DR_ + j];
    float c1 = cosb[s * DR_ + j + 32], s1 = sinb[s * DR_ + j + 32];
    base[j]      = x * c0 - y * s0;
    base[j + 32] = y * c1 + x * s1;
}

// ---------------- tensor-core flash attention v2 ----------------
// CTA = 128 q-rows x 64 k-cols. 8 warps x 16 q-rows (full rows per warp).
// Q fragments in registers; K,V double-buffered cp.async; warp-local softmax.
#define AK_LD 196
#define AV_LD 68
#define AP_LD 68
// K0,K1: 64*196 each; V0,V1: 128*68 each; Ps: 128*68
#define AT_K0 0
#define AT_K1 (64 * AK_LD)
#define AT_V0 (2 * 64 * AK_LD)
#define AT_V1 (AT_V0 + 128 * AV_LD)
#define AT_PS (AT_V1 + 128 * AV_LD)
#define ATTN_SMEM_FLOATS (AT_PS + 128 * AP_LD)
#define ATTN_SMEM_BYTES  (ATTN_SMEM_FLOATS * 4)   // 204800

__global__ __launch_bounds__(256, 1) void attn_mma(
    const float* __restrict__ q, const float* __restrict__ kv,
    const float* __restrict__ ckv, const float* __restrict__ vt,
    float* __restrict__ ao)
{
    extern __shared__ float sm[];
    int qt = (int)gridDim.x - 1 - (int)blockIdx.x;   // longest CTAs first
    int h = blockIdx.y, b = blockIdx.z;
    int tid = threadIdx.x, warp = tid >> 5, lane = tid & 31;
    int qs = warp * 16;
    int r  = lane >> 2, qd = lane & 3;

    int a_row = ((lane >> 3) & 1) * 8 + (lane & 7);
    int a_col = ((lane >> 4) & 1) * 4;
    uint32_t smem_base = (uint32_t)__cvta_generic_to_shared(sm);
    uint32_t k0_u = smem_base + AT_K0 * 4;
    uint32_t k1_u = smem_base + AT_K1 * 4;
    uint32_t v0_u = smem_base + AT_V0 * 4;
    uint32_t v1_u = smem_base + AT_V1 * 4;
    float* Ps = sm + AT_PS;

    int qbase = b * S_ + qt * 128;
    const float* vtp = &vt[(size_t)(b * NH_ + h) * DV_ * S_];

    // ---- stage Q [128][192] into K0||K1 region (25088 floats), tf32+scale ----
    for (int i = tid; i < 128 * 48; i += 256) {
        int row = i / 48, dq = (i - row * 48) * 4;
        float4 v = *(const float4*)&q[(size_t)(qbase + row) * QW + h * DQK_ + dq];
        uint4 u = make_uint4(f2tf(v.x * SCALE_CONST), f2tf(v.y * SCALE_CONST),
                             f2tf(v.z * SCALE_CONST), f2tf(v.w * SCALE_CONST));
        *(uint4*)&sm[row * AK_LD + dq] = u;
    }
    __syncthreads();

    // ---- extract Q fragments to registers (16 rows x 192 = 24 ldsm.x4) ----
    uint32_t af[24][4];
#pragma unroll
    for (int ks = 0; ks < 24; ks++)
        ldsm4(af[ks], smem_base + ((qs + a_row) * AK_LD + ks * 8 + a_col) * 4);
    __syncthreads();   // all warps done reading Q before K(0) overwrites

    // K issue: 64 rows x 48 float4-chunks = 12/thread
#define ATTN_ISSUE_K(ktile, kdst_u)                                                \
    do {                                                                           \
        int kb2 = b * S_ + (ktile) * 64;                                           \
        _Pragma("unroll")                                                          \
        for (int i = 0; i < 12; i++) {                                             \
            int c = tid + i * 256;                                                 \
            int row = c / 48, j = c - row * 48;                                    \
            const float* src = (j < 32)                                            \
                ? &kv[(size_t)(kb2 + row) * KVW + h * 256 + j * 4]                 \
                : &ckv[(size_t)(kb2 + row) * CKVW + KVLR_ + (j - 32) * 4];         \
            cpa16((kdst_u) + (row * AK_LD + j * 4) * 4, src);                      \
        }                                                                          \
    } while (0)

    // V issue: 128 vd-rows x 16 float4-chunks = 8/thread
#define ATTN_ISSUE_V(ktile, vdst_u)                                                \
    do {                                                                           \
        _Pragma("unroll")                                                          \
        for (int i = 0; i < 8; i++) {                                              \
            int c = tid + i * 256;                                                 \
            int vd = c >> 4, j = c & 15;                                           \
            cpa16((vdst_u) + (vd * AV_LD + j * 4) * 4,                             \
                  &vtp[(size_t)vd * S_ + (ktile) * 64 + j * 4]);                   \
        }                                                                          \
    } while (0)

    // prologue: tile 0 into buffer 0
    ATTN_ISSUE_K(0, k0_u);
    ATTN_ISSUE_V(0, v0_u);
    CP_COMMIT();

    float4 o[16];
#pragma unroll
    for (int i = 0; i < 16; i++) o[i] = make_float4(0.f, 0.f, 0.f, 0.f);
    float m_r = -1e30f, m_r8 = -1e30f, l_r = 0.f, l_r8 = 0.f;

    int lastk = 2 * qt + 1;
    for (int kt = 0; kt <= lastk; kt++) {
        __syncthreads();   // close reads of buffer (kt+1)&1 from tile kt-1
        bool doiss = (kt + 1 <= lastk);
        if (doiss) {
            ATTN_ISSUE_K(kt + 1, ((kt + 1) & 1) ? k1_u : k0_u);
            ATTN_ISSUE_V(kt + 1, ((kt + 1) & 1) ? v1_u : v0_u);
            CP_COMMIT();
            CP_WAIT1();
        } else {
            CP_WAIT0();
        }
        __syncthreads();   // tile kt data visible to all

        const float* Kb = (kt & 1) ? (sm + AT_K1) : (sm + AT_K0);
        const float* Vb = (kt & 1) ? (sm + AT_V1) : (sm + AT_V0);

        // ---- S = Q @ K^T : 16 rows x 64 cols per warp ----
        float4 s4[8];
#pragma unroll
        for (int nt = 0; nt < 8; nt++) s4[nt] = make_float4(0.f, 0.f, 0.f, 0.f);
#pragma unroll
        for (int ks = 0; ks < 24; ks++) {
#pragma unroll
            for (int nt = 0; nt < 8; nt++) {
                const float* p = &Kb[(nt * 8 + r) * AK_LD + ks * 8 + qd];
                mma_tf32(s4[nt], af[ks], f2tf(p[0]), f2tf(p[4]));
            }
        }

        // ---- causal mask (only the top two tiles can cross the diagonal) ----
        if (kt >= 2 * qt) {
            int thr  = qt * 128 + qs + r - kt * 64;       // col > thr  -> mask
            int thr8 = thr + 8;
#pragma unroll
            for (int nt = 0; nt < 8; nt++) {
                int c0 = nt * 8 + 2 * qd;
                if (c0     > thr)  s4[nt].x = -1e30f;
                if (c0 + 1 > thr)  s4[nt].y = -1e30f;
                if (c0     > thr8) s4[nt].z = -1e30f;
                if (c0 + 1 > thr8) s4[nt].w = -1e30f;
            }
        }

        // ---- warp-local online softmax (rows fully owned by this warp) ----
        float lm_r = -1e30f, lm_r8 = -1e30f;
#pragma unroll
        for (int nt = 0; nt < 8; nt++) {
            lm_r  = fmaxf(lm_r,  fmaxf(s4[nt].x, s4[nt].y));
            lm_r8 = fmaxf(lm_r8, fmaxf(s4[nt].z, s4[nt].w));
        }
        lm_r  = fmaxf(lm_r,  __shfl_xor_sync(0xffffffffu, lm_r, 1));
        lm_r  = fmaxf(lm_r,  __shfl_xor_sync(0xffffffffu, lm_r, 2));
        lm_r8 = fmaxf(lm_r8, __shfl_xor_sync(0xffffffffu, lm_r8, 1));
        lm_r8 = fmaxf(lm_r8, __shfl_xor_sync(0xffffffffu, lm_r8, 2));
        float mn_r  = fmaxf(m_r,  lm_r);
        float mn_r8 = fmaxf(m_r8, lm_r8);
        float al_r  = __expf(m_r - mn_r);
        float al_r8 = __expf(m_r8 - mn_r8);
        m_r = mn_r; m_r8 = mn_r8;

        float ps_r = 0.f, ps_r8 = 0.f;
#pragma unroll
        for (int nt = 0; nt < 8; nt++) {
            float px = __expf(s4[nt].x - mn_r);
            float py = __expf(s4[nt].y - mn_r);
            float pz = __expf(s4[nt].z - mn_r8);
            float pw = __expf(s4[nt].w - mn_r8);
            ps_r  += px + py;
            ps_r8 += pz + pw;
            int col = nt * 8 + 2 * qd;
            *(uint2*)&Ps[(qs + r) * AP_LD + col]     = make_uint2(f2tf(px), f2tf(py));
            *(uint2*)&Ps[(qs + r + 8) * AP_LD + col] = make_uint2(f2tf(pz), f2tf(pw));
        }
        ps_r  += __shfl_xor_sync(0xffffffffu, ps_r, 1);
        ps_r  += __shfl_xor_sync(0xffffffffu, ps_r, 2);
        ps_r8 += __shfl_xor_sync(0xffffffffu, ps_r8, 1);
        ps_r8 += __shfl_xor_sync(0xffffffffu, ps_r8, 2);
        l_r  = l_r  * al_r  + ps_r;
        l_r8 = l_r8 * al_r8 + ps_r8;
        __syncwarp();   // Ps rows (warp-private) written before ldsm reads

        // ---- O = O*al + P @ V ----
#pragma unroll
        for (int nt = 0; nt < 16; nt++) {
            o[nt].x *= al_r;  o[nt].y *= al_r;
            o[nt].z *= al_r8; o[nt].w *= al_r8;
        }
#pragma unroll
        for (int ks = 0; ks < 8; ks++) {
            uint32_t pf[4];
            ldsm4(pf, smem_base + (AT_PS + (qs + a_row) * AP_LD + ks * 8 + a_col) * 4);
#pragma unroll
            for (int nt = 0; nt < 16; nt++) {
                const float* p = &Vb[(nt * 8 + r) * AV_LD + ks * 8 + qd];
                mma_tf32(o[nt], pf, f2tf(p[0]), f2tf(p[4]));
            }
        }
    }
#undef ATTN_ISSUE_K
#undef ATTN_ISSUE_V

    // ---- epilogue: rows fully owned -> direct global write ----
    float inv_r  = 1.f / l_r;
    float inv_r8 = 1.f / l_r8;
#pragma unroll
    for (int nt = 0; nt < 16; nt++) {
        int col = nt * 8 + 2 * qd;
        size_t row0 = (size_t)(qbase + qs + r);
        *(float2*)&ao[row0 * AOW + h * DV_ + col] =
            make_float2(o[nt].x * inv_r, o[nt].y * inv_r);
        *(float2*)&ao[(row0 + 8) * AOW + h * DV_ + col] =
            make_float2(o[nt].z * inv_r8, o[nt].w * inv_r8);
    }
}

// ---------------- launch ----------------
extern "C" void kernel_launch(void* const* d_in, const int* in_sizes, int n_in,
                              void* d_out, int out_size)
{
    const float* hidden = (const float*)d_in[0];
    const float* cosb   = (const float*)d_in[2];
    const float* sinb   = (const float*)d_in[3];
    const float* w_qa   = (const float*)d_in[4];
    const float* qa_ln  = (const float*)d_in[5];
    const float* w_qb   = (const float*)d_in[6];
    const float* w_kva  = (const float*)d_in[7];
    const float* kva_ln = (const float*)d_in[8];
    const float* w_kvb  = (const float*)d_in[9];
    const float* w_o    = (const float*)d_in[10];
    float* out = (float*)d_out;

    float *qa, *ckv, *qbuf, *kvbuf, *ao, *vt;
    cudaGetSymbolAddress((void**)&qa,    g_qa);
    cudaGetSymbolAddress((void**)&ckv,   g_ckv);
    cudaGetSymbolAddress((void**)&qbuf,  g_q);
    cudaGetSymbolAddress((void**)&kvbuf, g_kv);
    cudaGetSymbolAddress((void**)&ao,    g_ao);
    cudaGetSymbolAddress((void**)&vt,    g_vt);

    cudaFuncSetAttribute(attn_mma, cudaFuncAttributeMaxDynamicSharedMemorySize,
                         ATTN_SMEM_BYTES);
    cudaFuncSetAttribute(gemm_tf32, cudaFuncAttributeMaxDynamicSharedMemorySize,
                         GEMM_SMEM_BYTES);

    // 1. q_a = hidden @ w_qa
    gemm_tf32<<<dim3(QLR_ / 128, MTOT / 128), 256, GEMM_SMEM_BYTES>>>(
        hidden, HID_, w_qa, QLR_, qa, QLR_, MTOT, QLR_, HID_, nullptr);
    // 2. ckv = hidden @ w_kva
    gemm_tf32<<<dim3((CKVW + 127) / 128, MTOT / 128), 256, GEMM_SMEM_BYTES>>>(
        hidden, HID_, w_kva, CKVW, ckv, CKVW, MTOT, CKVW, HID_, nullptr);
    // 3. rmsnorms
    rmsnorm_kernel<<<MTOT, 256>>>(qa, QLR_, QLR_, qa_ln);
    rmsnorm_kernel<<<MTOT, 256>>>(ckv, CKVW, KVLR_, kva_ln);
    // 4. q = qa_norm @ w_qb
    gemm_tf32<<<dim3(QW / 128, MTOT / 128), 256, GEMM_SMEM_BYTES>>>(
        qa, QLR_, w_qb, QW, qbuf, QW, MTOT, QW, QLR_, nullptr);
    // 5. kv = ckv_norm @ w_kvb  (V half scattered transposed into vt)
    gemm_tf32<<<dim3(KVW / 128, MTOT / 128), 256, GEMM_SMEM_BYTES>>>(
        ckv, CKVW, w_kvb, KVW, kvbuf, KVW, MTOT, KVW, KVLR_, vt);
    // 6. RoPE
    rope_q_kernel<<<(MTOT * NH_ * 32 + 255) / 256, 256>>>(qbuf, cosb, sinb);
    rope_k_kernel<<<(MTOT * 32 + 255) / 256, 256>>>(ckv, cosb, sinb);
    // 7. attention (tensor core, Q-in-registers, 128x64 tiles)
    attn_mma<<<dim3(S_ / 128, NH_, B_), 256, ATTN_SMEM_BYTES>>>(qbuf, kvbuf, ckv, vt, ao);
    // 8. out = ao @ w_o
    gemm_tf32<<<dim3(HID_ / 128, MTOT / 128), 256, GEMM_SMEM_BYTES>>>(
        ao, AOW, w_o, HID_, out, HID_, MTOT, HID_, AOW, nullptr);
}

// round 10
// speedup vs baseline: 1.1877x; 1.1877x over previous
#include <cuda_runtime.h>
#include <math.h>
#include <stdint.h>

#define B_    2
#define S_    2048
#define HID_  2048
#define NH_   16
#define QLR_  1536
#define KVLR_ 512
#define DN_   128
#define DR_   64
#define DV_   128
#define DQK_  192
#define MTOT  (B_ * S_)            // 4096
#define CKVW  (KVLR_ + DR_)        // 576
#define QW    (NH_ * DQK_)         // 3072
#define KVW   (NH_ * (DN_ + DV_))  // 4096
#define AOW   (NH_ * DV_)          // 2048
#define SCALE_CONST 0.07216878364870322f   // 192^-0.5

// ---------------- scratch (no allocation allowed) ----------------
__device__ float g_qa [(size_t)MTOT * QLR_];
__device__ float g_ckv[(size_t)MTOT * CKVW];
__device__ float g_q  [(size_t)MTOT * QW];
__device__ float g_kv [(size_t)MTOT * KVW];
__device__ float g_ao [(size_t)MTOT * AOW];
__device__ float g_vt [(size_t)B_ * NH_ * DV_ * S_];   // V transposed: [b][h][vd][s]

// ---------------- helpers ----------------
__device__ __forceinline__ uint32_t f2tf(float f) {
    uint32_t u;
    asm("cvt.rna.tf32.f32 %0, %1;" : "=r"(u) : "f"(f));
    return u;
}

__device__ __forceinline__ void ldsm4(uint32_t* r, uint32_t addr) {
    asm volatile("ldmatrix.sync.aligned.m8n8.x4.shared.b16 {%0,%1,%2,%3},[%4];"
                 : "=r"(r[0]), "=r"(r[1]), "=r"(r[2]), "=r"(r[3]) : "r"(addr));
}

__device__ __forceinline__ void mma_tf32(float4& d, const uint32_t* a, uint32_t b0, uint32_t b1) {
    asm volatile("mma.sync.aligned.m16n8k8.row.col.f32.tf32.tf32.f32 "
                 "{%0,%1,%2,%3},{%4,%5,%6,%7},{%8,%9},{%0,%1,%2,%3};"
                 : "+f"(d.x), "+f"(d.y), "+f"(d.z), "+f"(d.w)
                 : "r"(a[0]), "r"(a[1]), "r"(a[2]), "r"(a[3]), "r"(b0), "r"(b1));
}

__device__ __forceinline__ void cpa16(uint32_t dst, const void* src) {
    asm volatile("cp.async.cg.shared.global [%0], [%1], 16;" :: "r"(dst), "l"(src));
}
#define CP_COMMIT() asm volatile("cp.async.commit_group;")
#define CP_WAIT0()  asm volatile("cp.async.wait_group 0;")
#define CP_WAIT1()  asm volatile("cp.async.wait_group 1;")

// ---------------- tf32 GEMM: C[M,N] = A[M,K] @ Bm[K,N] ----------------
// BM=128 BN=128 BK=32, 256 threads (8 warps = 2m x 4n), warp tile 64x32.
// 3-stage cp.async pipeline, raw fp32 in smem, tf32 cvt at fragment load.
#define GBM 128
#define GBN 128
#define GBK 32
#define ALD 36
#define BLD 132
#define GEMM_A_FLOATS (GBM * ALD)   // 4608
#define GEMM_B_FLOATS (GBK * BLD)   // 4224
#define GEMM_SMEM_BYTES (3 * (GEMM_A_FLOATS + GEMM_B_FLOATS) * 4)   // 105984

__global__ __launch_bounds__(256, 2) void gemm_tf32(
    const float* __restrict__ A, int lda,
    const float* __restrict__ Bm, int ldb,
    float* __restrict__ C, int ldc,
    int M, int N, int K,
    float* __restrict__ vtp)   // non-null: kvb mode, V half scattered transposed
{
    extern __shared__ float gsm[];
    float* As = gsm;
    float* Bs = gsm + 3 * GEMM_A_FLOATS;

    int tid = threadIdx.x;
    int m0 = blockIdx.y * GBM, n0 = blockIdx.x * GBN;
    int warp = tid >> 5, lane = tid & 31;
    int wm = (warp & 1) * 64, wn = (warp >> 1) * 32;
    int r = lane >> 2, qd = lane & 3;

    float4 acc[4][4];
#pragma unroll
    for (int i = 0; i < 4; i++)
#pragma unroll
        for (int j = 0; j < 4; j++) acc[i][j] = make_float4(0.f, 0.f, 0.f, 0.f);

    int a_row = ((lane >> 3) & 1) * 8 + (lane & 7);
    int a_col = ((lane >> 4) & 1) * 4;
    uint32_t as_u = (uint32_t)__cvta_generic_to_shared(As);
    uint32_t bs_u = (uint32_t)__cvta_generic_to_shared(Bs);

    int s_arow = tid >> 3, s_akc = (tid & 7) * 4;
    int s_krow = tid >> 5, bnc = (lane & 31) * 4;
    bool nok = (n0 + bnc) < N;

    int nk = K / GBK;

#define GEMM_ISSUE(stage, k0)                                                      \
    do {                                                                           \
        uint32_t ad = as_u + (uint32_t)(stage) * GEMM_A_FLOATS * 4;                \
        uint32_t bd = bs_u + (uint32_t)(stage) * GEMM_B_FLOATS * 4;                \
        _Pragma("unroll")                                                          \
        for (int it = 0; it < 4; it++) {                                           \
            int row = s_arow + it * 32;                                            \
            cpa16(ad + (row * ALD + s_akc) * 4,                                    \
                  &A[(size_t)(m0 + row) * lda + (k0) + s_akc]);                    \
        }                                                                          \
        if (nok) {                                                                 \
            _Pragma("unroll")                                                      \
            for (int it = 0; it < 4; it++) {                                       \
                int kk2 = s_krow + it * 8;                                         \
                cpa16(bd + (kk2 * BLD + bnc) * 4,                                  \
                      &Bm[(size_t)((k0) + kk2) * ldb + n0 + bnc]);                 \
            }                                                                      \
        }                                                                          \
    } while (0)

    GEMM_ISSUE(0, 0);
    CP_COMMIT();
    if (nk > 1) GEMM_ISSUE(1, GBK);
    CP_COMMIT();

    for (int t = 0; t < nk; t++) {
        CP_WAIT1();
        __syncthreads();
        if (t + 2 < nk) GEMM_ISSUE((t + 2) % 3, (t + 2) * GBK);
        CP_COMMIT();

        int s = t % 3;
        uint32_t a_base = as_u + (uint32_t)s * GEMM_A_FLOATS * 4;
        const float* bsp = Bs + s * GEMM_B_FLOATS;

#pragma unroll
        for (int ks = 0; ks < 4; ks++) {
            int kk = ks * 8;
            uint32_t af[4][4];
#pragma unroll
            for (int mt = 0; mt < 4; mt++) {
                ldsm4(af[mt], a_base + ((wm + mt * 16 + a_row) * ALD + kk + a_col) * 4);
#pragma unroll
                for (int i = 0; i < 4; i++)
                    af[mt][i] = f2tf(__uint_as_float(af[mt][i]));
            }
            uint32_t b0[4], b1[4];
#pragma unroll
            for (int nt = 0; nt < 4; nt++) {
                const float* p = &bsp[(kk + qd) * BLD + wn + nt * 8 + r];
                b0[nt] = f2tf(p[0]);
                b1[nt] = f2tf(p[4 * BLD]);
            }
#pragma unroll
            for (int mt = 0; mt < 4; mt++)
#pragma unroll
                for (int nt = 0; nt < 4; nt++)
                    mma_tf32(acc[mt][nt], af[mt], b0[nt], b1[nt]);
        }
    }
#undef GEMM_ISSUE

    int row_l = lane >> 2, col_l = (lane & 3) * 2;
#pragma unroll
    for (int mt = 0; mt < 4; mt++) {
#pragma unroll
        for (int nt = 0; nt < 4; nt++) {
            int rr = m0 + wm + mt * 16 + row_l;
            int cc = n0 + wn + nt * 8 + col_l;
            if (cc >= N) continue;
            float4 a = acc[mt][nt];
            if (vtp != nullptr && (cc & 255) >= 128) {
                int hh = cc >> 8, vd = (cc & 255) - 128;
                int bb = rr >> 11, ss = rr & 2047;
                size_t base = ((size_t)(bb * NH_ + hh) * DV_ + vd) * (size_t)S_;
                vtp[base + ss]          = a.x;
                vtp[base + S_ + ss]     = a.y;
                vtp[base + ss + 8]      = a.z;
                vtp[base + S_ + ss + 8] = a.w;
            } else {
                *(float2*)&C[(size_t)rr * ldc + cc]       = make_float2(a.x, a.y);
                *(float2*)&C[(size_t)(rr + 8) * ldc + cc] = make_float2(a.z, a.w);
            }
        }
    }
}

// ---------------- rmsnorm (in place) ----------------
__global__ __launch_bounds__(256) void rmsnorm_kernel(float* __restrict__ x, int stride, int D,
                                                      const float* __restrict__ w)
{
    int row = blockIdx.x;
    float* p = x + (size_t)row * stride;
    float ss = 0.f;
    for (int i = threadIdx.x; i < D; i += 256) { float v = p[i]; ss += v * v; }
    __shared__ float red[8];
#pragma unroll
    for (int off = 16; off; off >>= 1) ss += __shfl_down_sync(0xffffffffu, ss, off);
    if ((threadIdx.x & 31) == 0) red[threadIdx.x >> 5] = ss;
    __syncthreads();
    if (threadIdx.x == 0) {
        float t = 0.f;
#pragma unroll
        for (int i = 0; i < 8; i++) t += red[i];
        red[0] = rsqrtf(t / (float)D + 1e-6f);
    }
    __syncthreads();
    float inv = red[0];
    for (int i = threadIdx.x; i < D; i += 256) p[i] = p[i] * inv * w[i];
}

// ---------------- RoPE ----------------
__global__ void rope_q_kernel(float* __restrict__ q, const float* __restrict__ cosb,
                              const float* __restrict__ sinb)
{
    int idx = blockIdx.x * blockDim.x + threadIdx.x;
    if (idx >= MTOT * NH_ * 32) return;
    int j = idx & 31;
    int h = (idx >> 5) & (NH_ - 1);
    int m = idx >> 9;
    int s = m & (S_ - 1);
    float* base = q + (size_t)m * QW + h * DQK_ + DN_;
    float x = base[j], y = base[j + 32];
    float c0 = cosb[s * DR_ + j],      s0 = sinb[s * DR_ + j];
    float c1 = cosb[s * DR_ + j + 32], s1 = sinb[s * DR_ + j + 32];
    base[j]      = x * c0 - y * s0;
    base[j + 32] = y * c1 + x * s1;
}

__global__ void rope_k_kernel(float* __restrict__ ckv, const float* __restrict__ cosb,
                              const float* __restrict__ sinb)
{
    int idx = blockIdx.x * blockDim.x + threadIdx.x;
    if (idx >= MTOT * 32) return;
    int j = idx & 31;
    int m = idx >> 5;
    int s = m & (S_ - 1);
    float* base = ckv + (size_t)m * CKVW + KVLR_;
    float x = base[j], y = base[j + 32];
    float c0 = cosb[s * DR_ + j],      s0 = sinb[s * DR_ + j];
    float c1 = cosb[s * DR_ + j + 32], s1 = sinb[s * DR_ + j + 32];
    base[j]      = x * c0 - y * s0;
    base[j + 32] = y * c1 + x * s1;
}

// ---------------- tensor-core flash attention (R7 structure, cp.async pipelined) ----------------
#define AQ_LD 196
#define AK_LD 196
#define AV_LD 68
#define AP_LD 68
#define AO_LD 132
// Q[64][196] + K0[64][196] + K1[64][196] + V[128][68] + P[64][68] + 256
#define ATTN_SMEM_FLOATS (3 * 64 * AQ_LD + 128 * AV_LD + 64 * AP_LD + 256)
#define ATTN_SMEM_BYTES  (ATTN_SMEM_FLOATS * 4)

__global__ __launch_bounds__(256, 1) void attn_mma(
    const float* __restrict__ q, const float* __restrict__ kv,
    const float* __restrict__ ckv, const float* __restrict__ vt,
    float* __restrict__ ao)
{
    extern __shared__ float sm[];
    float* Qs   = sm;                     // [64][196] tf32 (pre-converted)
    float* K0   = Qs + 64 * AQ_LD;        // [64][196] raw fp32 (cp.async)
    float* K1   = K0 + 64 * AK_LD;
    float* Vt   = K1 + 64 * AK_LD;        // [128][68] raw fp32 (cp.async)
    float* Ps   = Vt + 128 * AV_LD;       // [64][68]  tf32
    float* mbuf = Ps + 64 * AP_LD;        // [2][64]
    float* lbuf = mbuf + 128;             // [2][64]

    int qt = (int)gridDim.x - 1 - (int)blockIdx.x;   // longest CTAs first
    int h = blockIdx.y, b = blockIdx.z;
    int tid = threadIdx.x, warp = tid >> 5, lane = tid & 31;
    int qs = (warp & 3) * 16;
    int kh = warp >> 2;
    int r  = lane >> 2, qd = lane & 3;

    int a_row = ((lane >> 3) & 1) * 8 + (lane & 7);
    int a_col = ((lane >> 4) & 1) * 4;
    uint32_t smem_base = (uint32_t)__cvta_generic_to_shared(sm);
    uint32_t ps_off = (uint32_t)((Ps - sm)) * 4;
    uint32_t k0_u = (uint32_t)__cvta_generic_to_shared(K0);
    uint32_t k1_u = (uint32_t)__cvta_generic_to_shared(K1);
    uint32_t vt_u = (uint32_t)__cvta_generic_to_shared(Vt);

    int qbase = b * S_ + qt * 64;
    const float* vtp = &vt[(size_t)(b * NH_ + h) * DV_ * S_];

    // K issue: 64 rows x 48 float4-chunks (32 from kv, 16 from roped ckv) = 12/thread
#define ATTN_ISSUE_K(ktile, kdst_u)                                                \
    do {                                                                           \
        int kb2 = b * S_ + (ktile) * 64;                                           \
        _Pragma("unroll")                                                          \
        for (int i = 0; i < 12; i++) {                                             \
            int c = tid + i * 256;                                                 \
            int row = c / 48, j = c - row * 48;                                    \
            const float* src = (j < 32)                                            \
                ? &kv[(size_t)(kb2 + row) * KVW + h * 256 + j * 4]                 \
                : &ckv[(size_t)(kb2 + row) * CKVW + KVLR_ + (j - 32) * 4];         \
            cpa16((kdst_u) + (row * AK_LD + j * 4) * 4, src);                      \
        }                                                                          \
    } while (0)

    // V issue: 128 vd-rows x 16 float4-chunks = 8/thread
#define ATTN_ISSUE_V(ktile)                                                        \
    do {                                                                           \
        _Pragma("unroll")                                                          \
        for (int i = 0; i < 8; i++) {                                              \
            int c = tid + i * 256;                                                 \
            int vd = c >> 4, j = c & 15;                                           \
            cpa16(vt_u + (vd * AV_LD + j * 4) * 4,                                 \
                  &vtp[(size_t)vd * S_ + (ktile) * 64 + j * 4]);                   \
        }                                                                          \
    } while (0)

    // stage Q (scaled, tf32) with regular loads
    for (int i = tid; i < 64 * 48; i += 256) {
        int qr = i / 48, dq = (i - qr * 48) * 4;
        float4 v = *(const float4*)&q[(size_t)(qbase + qr) * QW + h * DQK_ + dq];
        uint4 u = make_uint4(f2tf(v.x * SCALE_CONST), f2tf(v.y * SCALE_CONST),
                             f2tf(v.z * SCALE_CONST), f2tf(v.w * SCALE_CONST));
        *(uint4*)&Qs[qr * AQ_LD + dq] = u;
    }

    // prologue: K(0)
    ATTN_ISSUE_K(0, k0_u);
    CP_COMMIT();

    float4 o[16];
#pragma unroll
    for (int i = 0; i < 16; i++) o[i] = make_float4(0.f, 0.f, 0.f, 0.f);
    float m_r = -1e30f, m_r8 = -1e30f, l_r = 0.f, l_r8 = 0.f;

    for (int kt = 0; kt <= qt; kt++) {
        __syncthreads();   // close previous tile's smem reads (V, K buffers)
        if (kt + 1 <= qt) ATTN_ISSUE_K(kt + 1, ((kt + 1) & 1) ? k1_u : k0_u);
        ATTN_ISSUE_V(kt);
        CP_COMMIT();
        CP_WAIT1();        // K(kt) complete (this thread)
        __syncthreads();   // K(kt) visible to all

        const float* Kb = (kt & 1) ? K1 : K0;

        // S = Q @ K^T  (warp: 16 rows x 32 cols of its half)
        float4 s4[4];
#pragma unroll
        for (int nt = 0; nt < 4; nt++) s4[nt] = make_float4(0.f, 0.f, 0.f, 0.f);
#pragma unroll
        for (int ks = 0; ks < 24; ks++) {
            uint32_t af[4];
            ldsm4(af, smem_base + ((qs + a_row) * AQ_LD + ks * 8 + a_col) * 4);
#pragma unroll
            for (int nt = 0; nt < 4; nt++) {
                const float* p = &Kb[(kh * 32 + nt * 8 + r) * AK_LD + ks * 8 + qd];
                mma_tf32(s4[nt], af, f2tf(p[0]), f2tf(p[4]));
            }
        }

        if (kt == qt) {
#pragma unroll
            for (int nt = 0; nt < 4; nt++) {
                int c0 = kh * 32 + nt * 8 + 2 * qd;
                int row = qs + r;
                if (c0     > row)     s4[nt].x = -1e30f;
                if (c0 + 1 > row)     s4[nt].y = -1e30f;
                if (c0     > row + 8) s4[nt].z = -1e30f;
                if (c0 + 1 > row + 8) s4[nt].w = -1e30f;
            }
        }

        float lm_r = -1e30f, lm_r8 = -1e30f;
#pragma unroll
        for (int nt = 0; nt < 4; nt++) {
            lm_r  = fmaxf(lm_r,  fmaxf(s4[nt].x, s4[nt].y));
            lm_r8 = fmaxf(lm_r8, fmaxf(s4[nt].z, s4[nt].w));
        }
        lm_r  = fmaxf(lm_r,  __shfl_xor_sync(0xffffffffu, lm_r, 1));
        lm_r  = fmaxf(lm_r,  __shfl_xor_sync(0xffffffffu, lm_r, 2));
        lm_r8 = fmaxf(lm_r8, __shfl_xor_sync(0xffffffffu, lm_r8, 1));
        lm_r8 = fmaxf(lm_r8, __shfl_xor_sync(0xffffffffu, lm_r8, 2));
        if (qd == 0) {
            mbuf[kh * 64 + qs + r]     = lm_r;
            mbuf[kh * 64 + qs + r + 8] = lm_r8;
        }
        CP_WAIT0();        // V(kt) complete (this thread)
        __syncthreads();   // mbuf + V visible to all
        float mn_r  = fmaxf(m_r,  fmaxf(mbuf[qs + r],     mbuf[64 + qs + r]));
        float mn_r8 = fmaxf(m_r8, fmaxf(mbuf[qs + r + 8], mbuf[64 + qs + r + 8]));
        float al_r  = __expf(m_r - mn_r);
        float al_r8 = __expf(m_r8 - mn_r8);
        m_r = mn_r; m_r8 = mn_r8;

        float ps_r = 0.f, ps_r8 = 0.f;
#pragma unroll
        for (int nt = 0; nt < 4; nt++) {
            float px = __expf(s4[nt].x - mn_r);
            float py = __expf(s4[nt].y - mn_r);
            float pz = __expf(s4[nt].z - mn_r8);
            float pw = __expf(s4[nt].w - mn_r8);
            ps_r  += px + py;
            ps_r8 += pz + pw;
            int col = kh * 32 + nt * 8 + 2 * qd;
            *(uint2*)&Ps[(qs + r) * AP_LD + col]     = make_uint2(f2tf(px), f2tf(py));
            *(uint2*)&Ps[(qs + r + 8) * AP_LD + col] = make_uint2(f2tf(pz), f2tf(pw));
        }
        ps_r  += __shfl_xor_sync(0xffffffffu, ps_r, 1);
        ps_r  += __shfl_xor_sync(0xffffffffu, ps_r, 2);
        ps_r8 += __shfl_xor_sync(0xffffffffu, ps_r8, 1);
        ps_r8 += __shfl_xor_sync(0xffffffffu, ps_r8, 2);
        l_r  = l_r  * al_r  + ps_r;
        l_r8 = l_r8 * al_r8 + ps_r8;
        __syncwarp();

#pragma unroll
        for (int nt = 0; nt < 16; nt++) {
            o[nt].x *= al_r;  o[nt].y *= al_r;
            o[nt].z *= al_r8; o[nt].w *= al_r8;
        }
#pragma unroll
        for (int ks = 0; ks < 4; ks++) {
            uint32_t af[4];
            ldsm4(af, smem_base + ps_off + ((qs + a_row) * AP_LD + kh * 32 + ks * 8 + a_col) * 4);
#pragma unroll
            for (int nt = 0; nt < 16; nt++) {
                const float* p = &Vt[(nt * 8 + r) * AV_LD + kh * 32 + ks * 8 + qd];
                mma_tf32(o[nt], af, f2tf(p[0]), f2tf(p[4]));
            }
        }
    }
#undef ATTN_ISSUE_K
#undef ATTN_ISSUE_V

    // combine the two kc-halves
    __syncthreads();
    float* obuf = K0;   // reuse
    if (qd == 0) {
        lbuf[kh * 64 + qs + r]     = l_r;
        lbuf[kh * 64 + qs + r + 8] = l_r8;
    }
    if (kh == 1) {
#pragma unroll
        for (int nt = 0; nt < 16; nt++) {
            int col = nt * 8 + 2 * qd;
            *(float2*)&obuf[(qs + r) * AO_LD + col]     = make_float2(o[nt].x, o[nt].y);
            *(float2*)&obuf[(qs + r + 8) * AO_LD + col] = make_float2(o[nt].z, o[nt].w);
        }
    }
    __syncthreads();
    if (kh == 0) {
        float inv_r  = 1.f / (lbuf[qs + r]     + lbuf[64 + qs + r]);
        float inv_r8 = 1.f / (lbuf[qs + r + 8] + lbuf[64 + qs + r + 8]);
#pragma unroll
        for (int nt = 0; nt < 16; nt++) {
            int col = nt * 8 + 2 * qd;
            float2 p0 = *(float2*)&obuf[(qs + r) * AO_LD + col];
            float2 p1 = *(float2*)&obuf[(qs + r + 8) * AO_LD + col];
            size_t row0 = (size_t)(qbase + qs + r);
            *(float2*)&ao[row0 * AOW + h * DV_ + col] =
                make_float2((o[nt].x + p0.x) * inv_r, (o[nt].y + p0.y) * inv_r);
            *(float2*)&ao[(row0 + 8) * AOW + h * DV_ + col] =
                make_float2((o[nt].z + p1.x) * inv_r8, (o[nt].w + p1.y) * inv_r8);
        }
    }
}

// ---------------- launch ----------------
extern "C" void kernel_launch(void* const* d_in, const int* in_sizes, int n_in,
                              void* d_out, int out_size)
{
    const float* hidden = (const float*)d_in[0];
    const float* cosb   = (const float*)d_in[2];
    const float* sinb   = (const float*)d_in[3];
    const float* w_qa   = (const float*)d_in[4];
    const float* qa_ln  = (const float*)d_in[5];
    const float* w_qb   = (const float*)d_in[6];
    const float* w_kva  = (const float*)d_in[7];
    const float* kva_ln = (const float*)d_in[8];
    const float* w_kvb  = (const float*)d_in[9];
    const float* w_o    = (const float*)d_in[10];
    float* out = (float*)d_out;

    float *qa, *ckv, *qbuf, *kvbuf, *ao, *vt;
    cudaGetSymbolAddress((void**)&qa,    g_qa);
    cudaGetSymbolAddress((void**)&ckv,   g_ckv);
    cudaGetSymbolAddress((void**)&qbuf,  g_q);
    cudaGetSymbolAddress((void**)&kvbuf, g_kv);
    cudaGetSymbolAddress((void**)&ao,    g_ao);
    cudaGetSymbolAddress((void**)&vt,    g_vt);

    cudaFuncSetAttribute(attn_mma, cudaFuncAttributeMaxDynamicSharedMemorySize,
                         ATTN_SMEM_BYTES);
    cudaFuncSetAttribute(gemm_tf32, cudaFuncAttributeMaxDynamicSharedMemorySize,
                         GEMM_SMEM_BYTES);

    // side stream + events for the independent KV chain (created once; reused —
    // identical work is enqueued on every call, so behavior stays deterministic)
    static cudaStream_t s_kv = nullptr;
    static cudaEvent_t ev_fork = nullptr, ev_join = nullptr;
    if (s_kv == nullptr) {
        cudaStreamCreateWithFlags(&s_kv, cudaStreamNonBlocking);
        cudaEventCreateWithFlags(&ev_fork, cudaEventDisableTiming);
        cudaEventCreateWithFlags(&ev_join, cudaEventDisableTiming);
    }

    // fork: KV chain on s_kv, Q chain on the default (capture) stream
    cudaEventRecord(ev_fork, 0);
    cudaStreamWaitEvent(s_kv, ev_fork, 0);

    // ---- KV chain (s_kv) ----
    gemm_tf32<<<dim3((CKVW + 127) / 128, MTOT / 128), 256, GEMM_SMEM_BYTES, s_kv>>>(
        hidden, HID_, w_kva, CKVW, ckv, CKVW, MTOT, CKVW, HID_, nullptr);
    rmsnorm_kernel<<<MTOT, 256, 0, s_kv>>>(ckv, CKVW, KVLR_, kva_ln);
    gemm_tf32<<<dim3(KVW / 128, MTOT / 128), 256, GEMM_SMEM_BYTES, s_kv>>>(
        ckv, CKVW, w_kvb, KVW, kvbuf, KVW, MTOT, KVW, KVLR_, vt);
    rope_k_kernel<<<(MTOT * 32 + 255) / 256, 256, 0, s_kv>>>(ckv, cosb, sinb);
    cudaEventRecord(ev_join, s_kv);

    // ---- Q chain (default stream) ----
    gemm_tf32<<<dim3(QLR_ / 128, MTOT / 128), 256, GEMM_SMEM_BYTES>>>(
        hidden, HID_, w_qa, QLR_, qa, QLR_, MTOT, QLR_, HID_, nullptr);
    rmsnorm_kernel<<<MTOT, 256>>>(qa, QLR_, QLR_, qa_ln);
    gemm_tf32<<<dim3(QW / 128, MTOT / 128), 256, GEMM_SMEM_BYTES>>>(
        qa, QLR_, w_qb, QW, qbuf, QW, MTOT, QW, QLR_, nullptr);
    rope_q_kernel<<<(MTOT * NH_ * 32 + 255) / 256, 256>>>(qbuf, cosb, sinb);

    // join before attention
    cudaStreamWaitEvent(0, ev_join, 0);

    // attention (tensor core, cp.async pipelined, longest CTAs first)
    attn_mma<<<dim3(S_ / 64, NH_, B_), 256, ATTN_SMEM_BYTES>>>(qbuf, kvbuf, ckv, vt, ao);
    // out = ao @ w_o
    gemm_tf32<<<dim3(HID_ / 128, MTOT / 128), 256, GEMM_SMEM_BYTES>>>(
        ao, AOW, w_o, HID_, out, HID_, MTOT, HID_, AOW, nullptr);
}